// round 11
// baseline (speedup 1.0000x reference)
#include <cuda_runtime.h>
#include <math.h>
#include <stdint.h>

#define S_LEN 2048
#define HID   4096
#define NH    32
#define NKV   8
#define HD    128
#define TOPK  16

// ---------------- scratch (device globals: no allocations allowed) ----------
__device__ float g_Q[(size_t)S_LEN * HID];        // 32 MB
__device__ float g_K[(size_t)S_LEN * NKV * HD];   // 8 MB
__device__ float g_V[(size_t)S_LEN * NKV * HD];   // 8 MB
__device__ float g_attn[(size_t)S_LEN * HID];     // 32 MB
__device__ float g_cos[S_LEN * 64];
__device__ float g_sin[S_LEN * 64];

// ---------------- RoPE table (host/correctly-rounded math emulation) --------
// DO NOT TOUCH: this exact pipeline is what makes the kernel pass.
__global__ void rope_table_kernel() {
    int idx = blockIdx.x * blockDim.x + threadIdx.x;
    if (idx >= S_LEN * 64) return;
    int s = idx >> 6;
    int i = idx & 63;
    double expo = (double)(2 * i) / 128.0;            // exact
    float  p    = (float)pow(500000.0, expo);         // CR powf emulation
    float  inv  = __fdiv_rn(1.0f, p);
    float  ang  = __fmul_rn((float)s, inv);
    g_cos[idx] = (float)cos((double)ang);             // CR cosf emulation
    g_sin[idx] = (float)sin((double)ang);             // CR sinf emulation
}

// ---------------- RoPE apply (Q and K fused; explicit rn mul/add) -----------
__global__ void rope_apply_kernel(float* __restrict__ Qd, float* __restrict__ Kd) {
    int idx = blockIdx.x * blockDim.x + threadIdx.x;
    const int totq = S_LEN * NH * 64;
    const int totk = S_LEN * NKV * 64;
    if (idx >= totq + totk) return;
    float* X;
    int nheads;
    if (idx < totq) { X = Qd; nheads = NH; }
    else            { X = Kd; nheads = NKV; idx -= totq; }
    int i = idx & 63;
    int h = (idx >> 6) % nheads;
    int s = idx / (nheads * 64);
    size_t base = ((size_t)s * nheads + h) * HD + i;
    float c  = g_cos[(s << 6) + i];
    float sn = g_sin[(s << 6) + i];
    float x1 = X[base];
    float x2 = X[base + 64];
    float t1 = __fmul_rn(x1, c);
    float t2 = __fmul_rn(x2, sn);
    float u1 = __fmul_rn(x2, c);
    float u2 = __fmul_rn(x1, sn);
    X[base]      = __fadd_rn(t1, -t2);
    X[base + 64] = __fadd_rn(u1, u2);
}

// ---------------- fp32 SGEMM: C[M,N] = A[M,K] @ B[N,K]^T -------------------
// BM=BN=128, BK=16, 256 threads, 8x8 per thread, register prefetch +
// double-buffered smem. Arithmetic order = proven R6 chain.
__device__ __forceinline__ void sgemm_body(
    const float* __restrict__ A, const float* __restrict__ B,
    float* __restrict__ C, int M, int N, int K, int bm, int bn)
{
    __shared__ float As[2][16 * 132];  // [k][m], padded
    __shared__ float Bs[2][16 * 132];  // [k][n], padded

    const int tid = threadIdx.x;
    const int lr = tid >> 2;            // 0..63
    const int lc = (tid & 3) << 2;      // 0,4,8,12
    const int ty = tid >> 4;            // 0..15
    const int tx = tid & 15;            // 0..15

    float acc[8][8];
#pragma unroll
    for (int i = 0; i < 8; i++)
#pragma unroll
        for (int j = 0; j < 8; j++) acc[i][j] = 0.0f;

    const float* Ap = A + (size_t)(bm + lr) * K + lc;
    const float* Bp = B + (size_t)(bn + lr) * K + lc;

    {
        float4 a0 = *(const float4*)(Ap);
        float4 a1 = *(const float4*)(Ap + (size_t)64 * K);
        float4 b0 = *(const float4*)(Bp);
        float4 b1 = *(const float4*)(Bp + (size_t)64 * K);
        As[0][(lc + 0) * 132 + lr] = a0.x;
        As[0][(lc + 1) * 132 + lr] = a0.y;
        As[0][(lc + 2) * 132 + lr] = a0.z;
        As[0][(lc + 3) * 132 + lr] = a0.w;
        As[0][(lc + 0) * 132 + lr + 64] = a1.x;
        As[0][(lc + 1) * 132 + lr + 64] = a1.y;
        As[0][(lc + 2) * 132 + lr + 64] = a1.z;
        As[0][(lc + 3) * 132 + lr + 64] = a1.w;
        Bs[0][(lc + 0) * 132 + lr] = b0.x;
        Bs[0][(lc + 1) * 132 + lr] = b0.y;
        Bs[0][(lc + 2) * 132 + lr] = b0.z;
        Bs[0][(lc + 3) * 132 + lr] = b0.w;
        Bs[0][(lc + 0) * 132 + lr + 64] = b1.x;
        Bs[0][(lc + 1) * 132 + lr + 64] = b1.y;
        Bs[0][(lc + 2) * 132 + lr + 64] = b1.z;
        Bs[0][(lc + 3) * 132 + lr + 64] = b1.w;
    }
    __syncthreads();

    int cur = 0;
    for (int k0 = 0; k0 < K; k0 += 16) {
        float4 a0, a1, b0, b1;
        const bool more = (k0 + 16 < K);
        if (more) {
            a0 = *(const float4*)(Ap + k0 + 16);
            a1 = *(const float4*)(Ap + (size_t)64 * K + k0 + 16);
            b0 = *(const float4*)(Bp + k0 + 16);
            b1 = *(const float4*)(Bp + (size_t)64 * K + k0 + 16);
        }

        const float* Asc = As[cur];
        const float* Bsc = Bs[cur];
#pragma unroll
        for (int kk = 0; kk < 16; kk++) {
            float ar[8], br[8];
            *(float4*)(ar)     = *(const float4*)&Asc[kk * 132 + ty * 8];
            *(float4*)(ar + 4) = *(const float4*)&Asc[kk * 132 + ty * 8 + 4];
            *(float4*)(br)     = *(const float4*)&Bsc[kk * 132 + tx * 8];
            *(float4*)(br + 4) = *(const float4*)&Bsc[kk * 132 + tx * 8 + 4];
#pragma unroll
            for (int i = 0; i < 8; i++)
#pragma unroll
                for (int j = 0; j < 8; j++)
                    acc[i][j] = fmaf(ar[i], br[j], acc[i][j]);
        }

        if (more) {
            int nxt = cur ^ 1;
            As[nxt][(lc + 0) * 132 + lr] = a0.x;
            As[nxt][(lc + 1) * 132 + lr] = a0.y;
            As[nxt][(lc + 2) * 132 + lr] = a0.z;
            As[nxt][(lc + 3) * 132 + lr] = a0.w;
            As[nxt][(lc + 0) * 132 + lr + 64] = a1.x;
            As[nxt][(lc + 1) * 132 + lr + 64] = a1.y;
            As[nxt][(lc + 2) * 132 + lr + 64] = a1.z;
            As[nxt][(lc + 3) * 132 + lr + 64] = a1.w;
            Bs[nxt][(lc + 0) * 132 + lr] = b0.x;
            Bs[nxt][(lc + 1) * 132 + lr] = b0.y;
            Bs[nxt][(lc + 2) * 132 + lr] = b0.z;
            Bs[nxt][(lc + 3) * 132 + lr] = b0.w;
            Bs[nxt][(lc + 0) * 132 + lr + 64] = b1.x;
            Bs[nxt][(lc + 1) * 132 + lr + 64] = b1.y;
            Bs[nxt][(lc + 2) * 132 + lr + 64] = b1.z;
            Bs[nxt][(lc + 3) * 132 + lr + 64] = b1.w;
            __syncthreads();
            cur = nxt;
        }
    }

#pragma unroll
    for (int i = 0; i < 8; i++) {
        size_t row = (size_t)(bm + ty * 8 + i) * N + bn + tx * 8;
        float4 v0 = make_float4(acc[i][0], acc[i][1], acc[i][2], acc[i][3]);
        float4 v1 = make_float4(acc[i][4], acc[i][5], acc[i][6], acc[i][7]);
        *(float4*)&C[row]     = v0;
        *(float4*)&C[row + 4] = v1;
    }
}

__global__ __launch_bounds__(256, 2) void sgemm_nt(
    const float* __restrict__ A, const float* __restrict__ B,
    float* __restrict__ C, int M, int N, int K)
{
    sgemm_body(A, B, C, M, N, K, blockIdx.y * 128, blockIdx.x * 128);
}

// Q, K, V projections fused: grid.x = 32 (Q) + 8 (K) + 8 (V)
__global__ __launch_bounds__(256, 2) void sgemm_qkv(
    const float* __restrict__ A,
    const float* __restrict__ Wq, const float* __restrict__ Wk,
    const float* __restrict__ Wv,
    float* __restrict__ Qo, float* __restrict__ Ko, float* __restrict__ Vo)
{
    int bx = blockIdx.x;
    const float* B;
    float* C;
    int N, bn;
    if (bx < 32)      { B = Wq; C = Qo; N = HID;      bn = bx * 128; }
    else if (bx < 40) { B = Wk; C = Ko; N = NKV * HD; bn = (bx - 32) * 128; }
    else              { B = Wv; C = Vo; N = NKV * HD; bn = (bx - 40) * 128; }
    sgemm_body(A, B, C, S_LEN, N, HID, blockIdx.y * 128, bn);
}

// ---------------- fused top-k attention ------------------------------------
// grid (S/128, NH), 256 threads. Q/K transposed smem [d][row]; COALESCED
// gmem loads (sgemm-style: 4 lanes/line) + strided STS transpose.
// Compute loop and top-k scan identical to R10 -> bitwise-same results.
#define APAD 132

__global__ __launch_bounds__(256) void attn_kernel(
    const float* __restrict__ Q, const float* __restrict__ Kd,
    const float* __restrict__ V, float* __restrict__ O)
{
    extern __shared__ float sm[];
    float* Qs = sm;                        // [128][APAD]  Qs[d*APAD + qr]
    float* Ks = Qs + 128 * APAD;           // [128][APAD]  Ks[d*APAD + kc]
    float* Ss = Ks + 128 * APAD;           // [128][128]
    float* Tv = Ss + 128 * 128;            // [128][16]
    int*   Ti = (int*)(Tv + 128 * TOPK);   // [128][16]

    const int tid = threadIdx.x;
    const int h   = blockIdx.y;
    const int kvh = h >> 2;
    const int q0  = blockIdx.x * 128;
    const float sqrtd = 11.313708498984761f;  // f32(sqrt(128))

    const int lr  = tid >> 2;           // 0..63 (row within half-tile)
    const int lc4 = (tid & 3) << 2;     // 0,4,8,12 (col group)

    // load Q tile transposed, coalesced: 8 passes over 16-col groups
#pragma unroll
    for (int p = 0; p < 8; p++) {
        int cb = p * 16 + lc4;
        float4 v0 = *(const float4*)&Q[((size_t)(q0 + lr) * NH + h) * HD + cb];
        float4 v1 = *(const float4*)&Q[((size_t)(q0 + lr + 64) * NH + h) * HD + cb];
        Qs[(cb + 0) * APAD + lr] = v0.x;
        Qs[(cb + 1) * APAD + lr] = v0.y;
        Qs[(cb + 2) * APAD + lr] = v0.z;
        Qs[(cb + 3) * APAD + lr] = v0.w;
        Qs[(cb + 0) * APAD + lr + 64] = v1.x;
        Qs[(cb + 1) * APAD + lr + 64] = v1.y;
        Qs[(cb + 2) * APAD + lr + 64] = v1.z;
        Qs[(cb + 3) * APAD + lr + 64] = v1.w;
    }
    if (tid < 128) {
#pragma unroll
        for (int j = 0; j < TOPK; j++) Tv[tid * TOPK + j] = -INFINITY;
    }
    float vmin = -INFINITY;
    int minpos = 0;

    const int ty = tid >> 4, tx = tid & 15;

    for (int kt = 0; kt < S_LEN / 128; kt++) {
        __syncthreads();   // prev top-k done with Ss; prev compute done with Ks
        // load K tile transposed, coalesced
#pragma unroll
        for (int p = 0; p < 8; p++) {
            int cb = p * 16 + lc4;
            float4 v0 = *(const float4*)&Kd[((size_t)(kt * 128 + lr) * NKV + kvh) * HD + cb];
            float4 v1 = *(const float4*)&Kd[((size_t)(kt * 128 + lr + 64) * NKV + kvh) * HD + cb];
            Ks[(cb + 0) * APAD + lr] = v0.x;
            Ks[(cb + 1) * APAD + lr] = v0.y;
            Ks[(cb + 2) * APAD + lr] = v0.z;
            Ks[(cb + 3) * APAD + lr] = v0.w;
            Ks[(cb + 0) * APAD + lr + 64] = v1.x;
            Ks[(cb + 1) * APAD + lr + 64] = v1.y;
            Ks[(cb + 2) * APAD + lr + 64] = v1.z;
            Ks[(cb + 3) * APAD + lr + 64] = v1.w;
        }
        __syncthreads();

        // 8x8 micro-tile scores over d = 0..127 (ascending chain, bitwise)
        float acc[8][8];
#pragma unroll
        for (int i = 0; i < 8; i++)
#pragma unroll
            for (int j = 0; j < 8; j++) acc[i][j] = 0.0f;

#pragma unroll 8
        for (int d = 0; d < 128; d++) {
            float ar[8], br[8];
            *(float4*)(ar)     = *(const float4*)&Qs[d * APAD + ty * 8];
            *(float4*)(ar + 4) = *(const float4*)&Qs[d * APAD + ty * 8 + 4];
            *(float4*)(br)     = *(const float4*)&Ks[d * APAD + tx * 8];
            *(float4*)(br + 4) = *(const float4*)&Ks[d * APAD + tx * 8 + 4];
#pragma unroll
            for (int i = 0; i < 8; i++)
#pragma unroll
                for (int j = 0; j < 8; j++)
                    acc[i][j] = fmaf(ar[i], br[j], acc[i][j]);
        }

#pragma unroll
        for (int i = 0; i < 8; i++) {
            float4 s0 = make_float4(__fdiv_rn(acc[i][0], sqrtd),
                                    __fdiv_rn(acc[i][1], sqrtd),
                                    __fdiv_rn(acc[i][2], sqrtd),
                                    __fdiv_rn(acc[i][3], sqrtd));
            float4 s1 = make_float4(__fdiv_rn(acc[i][4], sqrtd),
                                    __fdiv_rn(acc[i][5], sqrtd),
                                    __fdiv_rn(acc[i][6], sqrtd),
                                    __fdiv_rn(acc[i][7], sqrtd));
            *(float4*)&Ss[(ty * 8 + i) * 128 + tx * 8]     = s0;
            *(float4*)&Ss[(ty * 8 + i) * 128 + tx * 8 + 4] = s1;
        }
        __syncthreads();

        // per-row top-16 maintenance (threads 0..127), ascending col order
        if (tid < 128) {
            int base = kt * 128;
            float* tvp = Tv + tid * TOPK;
            int*   tip = Ti + tid * TOPK;
            const float* srow = Ss + tid * 128;
            for (int c = 0; c < 128; c++) {
                float s = srow[c];
                if (s > vmin) {
                    tvp[minpos] = s;
                    tip[minpos] = base + c;
                    vmin = tvp[0]; minpos = 0;
#pragma unroll
                    for (int j = 1; j < TOPK; j++) {
                        float t = tvp[j];
                        if (t < vmin) { vmin = t; minpos = j; }
                    }
                }
            }
        }
    }
    __syncthreads();

    // softmax over top-16 per row
    if (tid < 128) {
        float* tvp = Tv + tid * TOPK;
        float m = -INFINITY;
#pragma unroll
        for (int j = 0; j < TOPK; j++) m = fmaxf(m, tvp[j]);
        float ssum = 0.0f;
#pragma unroll
        for (int j = 0; j < TOPK; j++) {
            float e = expf(tvp[j] - m);
            tvp[j] = e;
            ssum += e;
        }
        float inv = __fdiv_rn(1.0f, ssum);
#pragma unroll
        for (int j = 0; j < TOPK; j++) tvp[j] = __fmul_rn(tvp[j], inv);
    }
    __syncthreads();

    // weighted V gather: 128 rows x 128 dims
#pragma unroll
    for (int it = 0; it < 64; it++) {
        int idx = tid + it * 256;
        int r = idx >> 7;
        int d = idx & 127;
        const float* tvp = Tv + r * TOPK;
        const int*   tip = Ti + r * TOPK;
        float acc = 0.0f;
#pragma unroll
        for (int j = 0; j < TOPK; j++) {
            float w = tvp[j];
            int ki = tip[j];
            acc = fmaf(w, V[((size_t)ki * NKV + kvh) * HD + d], acc);
        }
        O[((size_t)(q0 + r) * NH + h) * HD + d] = acc;
    }
}

// ---------------- launch ----------------------------------------------------
extern "C" void kernel_launch(void* const* d_in, const int* in_sizes, int n_in,
                              void* d_out, int out_size)
{
    const float* hidden = (const float*)d_in[0];
    const float* Wq = (const float*)d_in[1];
    const float* Wk = (const float*)d_in[2];
    const float* Wv = (const float*)d_in[3];
    const float* Wo = (const float*)d_in[4];
    float* out = (float*)d_out;

    float *q, *k, *v, *at;
    cudaGetSymbolAddress((void**)&q,  g_Q);
    cudaGetSymbolAddress((void**)&k,  g_K);
    cudaGetSymbolAddress((void**)&v,  g_V);
    cudaGetSymbolAddress((void**)&at, g_attn);

    rope_table_kernel<<<(S_LEN * 64 + 255) / 256, 256>>>();

    // fused Q/K/V projections: one launch, one tail
    dim3 gqkv(48, S_LEN / 128);                 // (48,16)
    sgemm_qkv<<<gqkv, 256>>>(hidden, Wq, Wk, Wv, q, k, v);

    int rope_total = S_LEN * (NH + NKV) * 64;
    rope_apply_kernel<<<(rope_total + 255) / 256, 256>>>(q, k);

    size_t smem = (size_t)(2 * 128 * APAD + 128 * 128 + 128 * TOPK) * 4
                + (size_t)128 * TOPK * 4;
    cudaFuncSetAttribute(attn_kernel, cudaFuncAttributeMaxDynamicSharedMemorySize,
                         (int)smem);
    attn_kernel<<<dim3(S_LEN / 128, NH), 256, smem>>>(q, k, v, at);

    dim3 gq(HID / 128, S_LEN / 128);            // (32,16)
    sgemm_nt<<<gq, 256>>>(at, Wo, out, S_LEN, HID, HID);
}